// round 3
// baseline (speedup 1.0000x reference)
#include <cuda_runtime.h>

#define CC 192
#define KK 64
#define HW_SHIFT 12   // H*W = 4096
#define LIK_BOUND 1e-9f

__device__ float g_lut[CC * KK];

__device__ __forceinline__ float softplusf(float x) {
    // stable softplus = max(x,0) + log1p(exp(-|x|))   (matches jax.nn.softplus)
    return fmaxf(x, 0.0f) + log1pf(expf(-fabsf(x)));
}

__global__ void build_lut_kernel(
    const float* __restrict__ cb,
    const float* __restrict__ m0, const float* __restrict__ m1,
    const float* __restrict__ m2, const float* __restrict__ m3,
    const float* __restrict__ m4,
    const float* __restrict__ b0, const float* __restrict__ b1,
    const float* __restrict__ b2, const float* __restrict__ b3,
    const float* __restrict__ b4,
    const float* __restrict__ f0, const float* __restrict__ f1,
    const float* __restrict__ f2, const float* __restrict__ f3)
{
    int t = blockIdx.x * blockDim.x + threadIdx.x;
    if (t >= CC * KK) return;
    int c = t / KK;
    int k = t % KK;
    float v = cb[k];

    // Transformed params shared by lower/upper evaluation
    float w0[3], w4[3], bb0[3], bb1[3], bb2[3], bb3[3], bb4;
    float t0[3], t1[3], t2[3], t3[3];
    float w1[9], w2[9], w3[9];
    #pragma unroll
    for (int j = 0; j < 3; j++) {
        w0[j]  = softplusf(m0[c * 3 + j]);
        w4[j]  = softplusf(m4[c * 3 + j]);
        bb0[j] = b0[c * 3 + j];
        bb1[j] = b1[c * 3 + j];
        bb2[j] = b2[c * 3 + j];
        bb3[j] = b3[c * 3 + j];
        t0[j]  = tanhf(f0[c * 3 + j]);
        t1[j]  = tanhf(f1[c * 3 + j]);
        t2[j]  = tanhf(f2[c * 3 + j]);
        t3[j]  = tanhf(f3[c * 3 + j]);
    }
    #pragma unroll
    for (int j = 0; j < 9; j++) {
        w1[j] = softplusf(m1[c * 9 + j]);
        w2[j] = softplusf(m2[c * 9 + j]);
        w3[j] = softplusf(m3[c * 9 + j]);
    }
    bb4 = b4[c];

    float outs[2];
    #pragma unroll
    for (int s = 0; s < 2; s++) {
        float u = v + (s == 0 ? -0.5f : 0.5f);
        float h[3], nt[3];
        // layer 0: 1 -> 3
        #pragma unroll
        for (int j = 0; j < 3; j++) {
            h[j] = w0[j] * u + bb0[j];
            h[j] += t0[j] * tanhf(h[j]);
        }
        // layer 1: 3 -> 3
        #pragma unroll
        for (int j = 0; j < 3; j++) {
            nt[j] = w1[j*3+0]*h[0] + w1[j*3+1]*h[1] + w1[j*3+2]*h[2] + bb1[j];
            nt[j] += t1[j] * tanhf(nt[j]);
        }
        #pragma unroll
        for (int j = 0; j < 3; j++) h[j] = nt[j];
        // layer 2: 3 -> 3
        #pragma unroll
        for (int j = 0; j < 3; j++) {
            nt[j] = w2[j*3+0]*h[0] + w2[j*3+1]*h[1] + w2[j*3+2]*h[2] + bb2[j];
            nt[j] += t2[j] * tanhf(nt[j]);
        }
        #pragma unroll
        for (int j = 0; j < 3; j++) h[j] = nt[j];
        // layer 3: 3 -> 3
        #pragma unroll
        for (int j = 0; j < 3; j++) {
            nt[j] = w3[j*3+0]*h[0] + w3[j*3+1]*h[1] + w3[j*3+2]*h[2] + bb3[j];
            nt[j] += t3[j] * tanhf(nt[j]);
        }
        #pragma unroll
        for (int j = 0; j < 3; j++) h[j] = nt[j];
        // layer 4: 3 -> 1 (no factor)
        outs[s] = w4[0]*h[0] + w4[1]*h[1] + w4[2]*h[2] + bb4;
    }

    float lo = outs[0], up = outs[1];
    float ssum = lo + up;
    float sg = (ssum > 0.0f) ? -1.0f : ((ssum < 0.0f) ? 1.0f : 0.0f);
    float su = 1.0f / (1.0f + expf(-sg * up));
    float sl = 1.0f / (1.0f + expf(-sg * lo));
    g_lut[t] = fmaxf(fabsf(su - sl), LIK_BOUND);
}

__global__ void quant_lik_kernel(
    const float4* __restrict__ x4,
    const float*  __restrict__ cb,
    float4* __restrict__ y4,
    float4* __restrict__ l4,
    long n4)
{
    __shared__ float scb[KK];
    if (threadIdx.x < KK) scb[threadIdx.x] = cb[threadIdx.x];
    __syncthreads();

    long i = (long)blockIdx.x * blockDim.x + threadIdx.x;
    if (i >= n4) return;

    float4 xv = x4[i];
    // element index = i*4; channel = (elem >> 12) % 192 == (i >> 10) % 192
    int c = (int)((i >> (HW_SHIFT - 2)) % CC);
    const float* __restrict__ lrow = g_lut + c * KK;

    float xs[4] = {xv.x, xv.y, xv.z, xv.w};
    float ys[4], ls[4];

    #pragma unroll
    for (int j = 0; j < 4; j++) {
        float xx = xs[j];
        // searchsorted(cb, xx) side='left' : first idx with cb[idx] >= xx, range [0,64]
        int lo = 0, hi = KK;
        #pragma unroll
        for (int it = 0; it < 7; it++) {
            if (lo < hi) {
                int mid = (lo + hi) >> 1;
                if (scb[mid] < xx) lo = mid + 1; else hi = mid;
            }
        }
        int il = min(max(lo - 1, 0), KK - 1);
        int ih = min(lo, KK - 1);
        float cl = scb[il], ch = scb[ih];
        bool pick_hi = fabsf(ch - xx) < fabsf(cl - xx);
        int k = pick_hi ? ih : il;
        ys[j] = pick_hi ? ch : cl;
        ls[j] = lrow[k];
    }

    y4[i] = make_float4(ys[0], ys[1], ys[2], ys[3]);
    l4[i] = make_float4(ls[0], ls[1], ls[2], ls[3]);
}

extern "C" void kernel_launch(void* const* d_in, const int* in_sizes, int n_in,
                              void* d_out, int out_size)
{
    // metadata order follows setup_inputs() dict insertion order:
    // x, codebook, m0, b0, f0, m1, b1, f1, m2, b2, f2, m3, b3, f3, m4, b4
    const float* x  = (const float*)d_in[0];
    const float* cb = (const float*)d_in[1];
    const float* m0 = (const float*)d_in[2];
    const float* b0 = (const float*)d_in[3];
    const float* f0 = (const float*)d_in[4];
    const float* m1 = (const float*)d_in[5];
    const float* b1 = (const float*)d_in[6];
    const float* f1 = (const float*)d_in[7];
    const float* m2 = (const float*)d_in[8];
    const float* b2 = (const float*)d_in[9];
    const float* f2 = (const float*)d_in[10];
    const float* m3 = (const float*)d_in[11];
    const float* b3 = (const float*)d_in[12];
    const float* f3 = (const float*)d_in[13];
    const float* m4 = (const float*)d_in[14];
    const float* b4 = (const float*)d_in[15];

    long total = (long)in_sizes[0];
    long n4 = total / 4;

    float* yhat = (float*)d_out;
    float* lik  = (float*)d_out + total;

    build_lut_kernel<<<(CC * KK + 255) / 256, 256>>>(
        cb, m0, m1, m2, m3, m4, b0, b1, b2, b3, b4, f0, f1, f2, f3);

    quant_lik_kernel<<<(int)((n4 + 255) / 256), 256>>>(
        (const float4*)x, cb, (float4*)yhat, (float4*)lik, n4);
}

// round 4
// speedup vs baseline: 1.1997x; 1.1997x over previous
#include <cuda_runtime.h>
#include <math_constants.h>

#define CC 192
#define KK 64
#define NBINS 2048
#define BIN_LO (-10.5f)
#define BIN_W  (21.0f / (float)NBINS)
#define BIN_INV ((float)NBINS / 21.0f)
#define LIK_BOUND 1e-9f

// {y, lik} per (channel, code)
__device__ float2 g_tab[CC * KK];
// midpoints (63 real + 1 INF sentinel)
__device__ float g_mid[KK];
// per-bin lower bound on k (with one-bin-back safety slack)
__device__ unsigned char g_k0[NBINS];

__device__ __forceinline__ float softplusf(float x) {
    return fmaxf(x, 0.0f) + log1pf(expf(-fabsf(x)));
}

__global__ void build_lut_kernel(
    const float* __restrict__ cb,
    const float* __restrict__ m0, const float* __restrict__ m1,
    const float* __restrict__ m2, const float* __restrict__ m3,
    const float* __restrict__ m4,
    const float* __restrict__ b0, const float* __restrict__ b1,
    const float* __restrict__ b2, const float* __restrict__ b3,
    const float* __restrict__ b4,
    const float* __restrict__ f0, const float* __restrict__ f1,
    const float* __restrict__ f2, const float* __restrict__ f3)
{
    int t = blockIdx.x * blockDim.x + threadIdx.x;

    // ---- midpoints ----
    if (t < KK) {
        g_mid[t] = (t < KK - 1) ? 0.5f * (cb[t] + cb[t + 1]) : CUDART_INF_F;
    }

    // ---- bin table: k0[bin] = #mids < binLeft(bin-1)  (slack = 1 bin) ----
    if (t < NBINS) {
        float bl = BIN_LO + (float)(t - 1) * BIN_W;
        int lo = 0, hi = KK - 1;  // search over 63 midpoints
        while (lo < hi) {
            int m = (lo + hi) >> 1;
            float mid = 0.5f * (cb[m] + cb[m + 1]);
            if (mid < bl) lo = m + 1; else hi = m;
        }
        g_k0[t] = (unsigned char)lo;
    }

    if (t >= CC * KK) return;
    int c = t / KK;
    int k = t % KK;
    float v = cb[k];

    float w0[3], w4[3], bb0[3], bb1[3], bb2[3], bb3[3], bb4;
    float t0[3], t1[3], t2[3], t3[3];
    float w1[9], w2[9], w3[9];
    #pragma unroll
    for (int j = 0; j < 3; j++) {
        w0[j]  = softplusf(m0[c * 3 + j]);
        w4[j]  = softplusf(m4[c * 3 + j]);
        bb0[j] = b0[c * 3 + j];
        bb1[j] = b1[c * 3 + j];
        bb2[j] = b2[c * 3 + j];
        bb3[j] = b3[c * 3 + j];
        t0[j]  = tanhf(f0[c * 3 + j]);
        t1[j]  = tanhf(f1[c * 3 + j]);
        t2[j]  = tanhf(f2[c * 3 + j]);
        t3[j]  = tanhf(f3[c * 3 + j]);
    }
    #pragma unroll
    for (int j = 0; j < 9; j++) {
        w1[j] = softplusf(m1[c * 9 + j]);
        w2[j] = softplusf(m2[c * 9 + j]);
        w3[j] = softplusf(m3[c * 9 + j]);
    }
    bb4 = b4[c];

    float outs[2];
    #pragma unroll
    for (int s = 0; s < 2; s++) {
        float u = v + (s == 0 ? -0.5f : 0.5f);
        float h[3], nt[3];
        #pragma unroll
        for (int j = 0; j < 3; j++) {
            h[j] = w0[j] * u + bb0[j];
            h[j] += t0[j] * tanhf(h[j]);
        }
        #pragma unroll
        for (int j = 0; j < 3; j++) {
            nt[j] = w1[j*3+0]*h[0] + w1[j*3+1]*h[1] + w1[j*3+2]*h[2] + bb1[j];
            nt[j] += t1[j] * tanhf(nt[j]);
        }
        #pragma unroll
        for (int j = 0; j < 3; j++) h[j] = nt[j];
        #pragma unroll
        for (int j = 0; j < 3; j++) {
            nt[j] = w2[j*3+0]*h[0] + w2[j*3+1]*h[1] + w2[j*3+2]*h[2] + bb2[j];
            nt[j] += t2[j] * tanhf(nt[j]);
        }
        #pragma unroll
        for (int j = 0; j < 3; j++) h[j] = nt[j];
        #pragma unroll
        for (int j = 0; j < 3; j++) {
            nt[j] = w3[j*3+0]*h[0] + w3[j*3+1]*h[1] + w3[j*3+2]*h[2] + bb3[j];
            nt[j] += t3[j] * tanhf(nt[j]);
        }
        #pragma unroll
        for (int j = 0; j < 3; j++) h[j] = nt[j];
        outs[s] = w4[0]*h[0] + w4[1]*h[1] + w4[2]*h[2] + bb4;
    }

    float lo = outs[0], up = outs[1];
    float ssum = lo + up;
    float sg = (ssum > 0.0f) ? -1.0f : ((ssum < 0.0f) ? 1.0f : 0.0f);
    float su = 1.0f / (1.0f + expf(-sg * up));
    float sl = 1.0f / (1.0f + expf(-sg * lo));
    float lik = fmaxf(fabsf(su - sl), LIK_BOUND);
    g_tab[t] = make_float2(v, lik);
}

// Each block = 256 threads x 4 float4 = 4096 elements = exactly one (n,c) plane.
__global__ void __launch_bounds__(256) quant_lik_kernel(
    const float4* __restrict__ x4,
    float4* __restrict__ y4,
    float4* __restrict__ l4)
{
    __shared__ float2 stab[KK];
    __shared__ float  smid[KK];
    __shared__ unsigned char sk0[NBINS];

    int tid = threadIdx.x;
    int c = blockIdx.x % CC;

    if (tid < KK) {
        stab[tid] = g_tab[c * KK + tid];
        smid[tid] = g_mid[tid];
    }
    {
        const int* gk = (const int*)g_k0;
        int* sk = (int*)sk0;
        sk[tid]       = gk[tid];
        sk[tid + 256] = gk[tid + 256];
    }
    __syncthreads();

    long base = (long)blockIdx.x * 1024 + tid;  // in float4 units; stride 256

    #pragma unroll
    for (int v = 0; v < 4; v++) {
        long i = base + v * 256;
        float4 xv = x4[i];
        float xs[4] = {xv.x, xv.y, xv.z, xv.w};
        float ys[4], ls[4];

        #pragma unroll
        for (int j = 0; j < 4; j++) {
            float xx = xs[j];
            int bin = __float2int_rd((xx - BIN_LO) * BIN_INV);
            bin = min(max(bin, 0), NBINS - 1);
            int k = sk0[bin];
            // branchless advance (covers the common <=3 mids of slack)
            k += (smid[k] < xx);
            k += (smid[k] < xx);
            k += (smid[k] < xx);
            // rare safety loop; smid[63] = +INF bounds k
            while (smid[k] < xx) k++;
            float2 yl = stab[k];
            ys[j] = yl.x;
            ls[j] = yl.y;
        }

        y4[i] = make_float4(ys[0], ys[1], ys[2], ys[3]);
        l4[i] = make_float4(ls[0], ls[1], ls[2], ls[3]);
    }
}

extern "C" void kernel_launch(void* const* d_in, const int* in_sizes, int n_in,
                              void* d_out, int out_size)
{
    // metadata order: x, codebook, m0, b0, f0, m1, b1, f1, m2, b2, f2, m3, b3, f3, m4, b4
    const float* x  = (const float*)d_in[0];
    const float* cb = (const float*)d_in[1];
    const float* m0 = (const float*)d_in[2];
    const float* b0 = (const float*)d_in[3];
    const float* f0 = (const float*)d_in[4];
    const float* m1 = (const float*)d_in[5];
    const float* b1 = (const float*)d_in[6];
    const float* f1 = (const float*)d_in[7];
    const float* m2 = (const float*)d_in[8];
    const float* b2 = (const float*)d_in[9];
    const float* f2 = (const float*)d_in[10];
    const float* m3 = (const float*)d_in[11];
    const float* b3 = (const float*)d_in[12];
    const float* f3 = (const float*)d_in[13];
    const float* m4 = (const float*)d_in[14];
    const float* b4 = (const float*)d_in[15];

    long total = (long)in_sizes[0];        // 16*192*64*64 = 12582912
    int nblocks = (int)(total / 4096);     // one (n,c) plane per block

    float* yhat = (float*)d_out;
    float* lik  = (float*)d_out + total;

    build_lut_kernel<<<48, 256>>>(
        cb, m0, m1, m2, m3, m4, b0, b1, b2, b3, b4, f0, f1, f2, f3);

    quant_lik_kernel<<<nblocks, 256>>>(
        (const float4*)x, (float4*)yhat, (float4*)lik);
}